// round 15
// baseline (speedup 1.0000x reference)
#include <cuda_runtime.h>
#include <cuda_fp16.h>
#include <cstddef>
#include <cstdint>

#define NN    100000
#define NEDGE 3200000
#define FEAT  256
#define HID   128
#define NOUT  64
#define HOPS  3
#define CAPO  ((size_t)NN * NOUT)

#define W_SCALE 32767.0f
#define W_INV   (1.0f / 32767.0f)

// 8 fp16 hop buffers (64-dim): s-dir y0..y3, t-dir y0..y3
__device__ __half    g_hbuf[8][CAPO];
__device__ int       g_deg[2][NN];
__device__ int       g_rowptr[2][NN + 1];
__device__ int       g_fill[2][NN];
__device__ int       g_bsum[2][128];
__device__ uint32_t  g_csr[2][NEDGE];   // packed: (nbr << 15) | q15(weight)
__device__ float     g_wc[2][FEAT][NOUT];   // folded W_in @ Wn_half
__device__ float     g_bc[2][NOUT];         // folded b_in @ Wn_half

// side stream + fork/join events (host objects; created once at load)
static cudaStream_t g_side = 0;
static cudaEvent_t  g_evFork = 0, g_evJoin = 0;
namespace {
struct StreamInit {
    StreamInit() {
        cudaStreamCreateWithFlags(&g_side, cudaStreamNonBlocking);
        cudaEventCreateWithFlags(&g_evFork, cudaEventDisableTiming);
        cudaEventCreateWithFlags(&g_evJoin, cudaEventDisableTiming);
    }
};
static StreamInit g_streamInit;
}

// ======================= weight folding =======================
__global__ __launch_bounds__(64)
void fold_kernel(const float* __restrict__ W_src, const float* __restrict__ b_src,
                 const float* __restrict__ W_tgt, const float* __restrict__ b_tgt,
                 const float* __restrict__ Wn, float* __restrict__ wc,
                 float* __restrict__ bc) {
    int dir = blockIdx.y;
    int i = blockIdx.x;          // 0..FEAT; FEAT => bias row
    int j = threadIdx.x;         // 0..63
    const float* W = dir ? W_tgt : W_src;
    const float* b = dir ? b_tgt : b_src;
    float acc = 0.f;
    if (i < FEAT) {
        for (int k = 0; k < HID; k++)
            acc += W[i * HID + k] * Wn[(size_t)(dir * HID + k) * NOUT + j];
        wc[(size_t)dir * FEAT * NOUT + (size_t)i * NOUT + j] = acc;
    } else {
        for (int k = 0; k < HID; k++)
            acc += b[k] * Wn[(size_t)(dir * HID + k) * NOUT + j];
        bc[dir * NOUT + j] = acc;
    }
}

// ======================= CSR build =======================
__global__ __launch_bounds__(256)
void hist_kernel(const int* __restrict__ erow, const int* __restrict__ ecol,
                 int* __restrict__ deg_s, int* __restrict__ deg_t, int E) {
    int e = blockIdx.x * blockDim.x + threadIdx.x;
    if (e < E) {
        atomicAdd(&deg_s[erow[e]], 1);
        atomicAdd(&deg_t[ecol[e]], 1);
    }
}

__global__ __launch_bounds__(1024)
void scan_chunk2(const int* __restrict__ deg_s, int* __restrict__ rp_s, int* __restrict__ bs_s,
                 const int* __restrict__ deg_t, int* __restrict__ rp_t, int* __restrict__ bs_t,
                 int n) {
    const int* in = blockIdx.y ? deg_t : deg_s;
    int* out = blockIdx.y ? rp_t : rp_s;
    int* bsum = blockIdx.y ? bs_t : bs_s;
    __shared__ int sh[1024];
    int t = threadIdx.x;
    int g = blockIdx.x * 1024 + t;
    int v = (g < n) ? in[g] : 0;
    sh[t] = v;
    __syncthreads();
    #pragma unroll
    for (int off = 1; off < 1024; off <<= 1) {
        int x = (t >= off) ? sh[t - off] : 0;
        __syncthreads();
        sh[t] += x;
        __syncthreads();
    }
    if (g < n) out[g] = sh[t] - v;
    if (t == 1023) bsum[blockIdx.x] = sh[1023];
}

__global__ __launch_bounds__(256)
void finalize2(int* __restrict__ rp_s, const int* __restrict__ bs_s, int* __restrict__ fil_s,
               int* __restrict__ rp_t, const int* __restrict__ bs_t, int* __restrict__ fil_t,
               int n, int nchunks, int total) {
    int* rowptr = blockIdx.y ? rp_t : rp_s;
    const int* bs = blockIdx.y ? bs_t : bs_s;
    int* fill = blockIdx.y ? fil_t : fil_s;
    __shared__ int sh[128];
    int t = threadIdx.x;
    if (t < 128) sh[t] = (t < nchunks) ? bs[t] : 0;
    __syncthreads();
    #pragma unroll
    for (int off = 1; off < 128; off <<= 1) {
        int x = (t >= off && t < 128) ? sh[t - off] : 0;
        __syncthreads();
        if (t < 128) sh[t] += x;
        __syncthreads();
    }
    int chunk = (blockIdx.x * 256) >> 10;
    int pre = chunk ? sh[chunk - 1] : 0;
    int g = blockIdx.x * 256 + t;
    if (g < n) {
        int v = rowptr[g] + pre;
        rowptr[g] = v;
        fill[g] = v;
    }
    if (g == n) rowptr[n] = total;
}

__device__ __forceinline__ void stcs_u32(uint32_t* addr, uint32_t v) {
    asm volatile("st.global.cs.u32 [%0], %1;" :: "l"(addr), "r"(v) : "memory");
}

__global__ __launch_bounds__(256)
void scatter_kernel(const int* __restrict__ erow, const int* __restrict__ ecol,
                    const float* __restrict__ ew,
                    int* __restrict__ fill_s, int* __restrict__ fill_t,
                    uint32_t* __restrict__ csr_s, uint32_t* __restrict__ csr_t, int E) {
    int e = blockIdx.x * blockDim.x + threadIdx.x;
    if (e >= E) return;
    int r = erow[e];
    int c = ecol[e];
    uint32_t qw = (uint32_t)__float2int_rn(ew[e] * W_SCALE);
    int ps = atomicAdd(&fill_s[r], 1);
    stcs_u32(csr_s + ps, ((uint32_t)c << 15) | qw);
    int pt = atomicAdd(&fill_t[c], 1);
    stcs_u32(csr_t + pt, ((uint32_t)r << 15) | qw);
}

// ======================= SPMM (64-dim fp16 gather, fp32 accumulate) =========
// FULL WARP per node: half-warps process two edges of the SAME node
// simultaneously (lanes 0-15 -> edge j, lanes 16-31 -> edge j+1), then a
// shfl_xor(16) butterfly combines the two partial sums. No cross-node
// divergence inside a warp; per-warp work ∝ own degree.
__global__ __launch_bounds__(256)
void spmm2_kernel(const int* __restrict__ rp_s, const int* __restrict__ rp_t,
                  const uint32_t* __restrict__ csr_s, const uint32_t* __restrict__ csr_t,
                  __half* __restrict__ hb, int h, int n) {
    int dir = blockIdx.y;
    const int* rowptr = dir ? rp_t : rp_s;
    const uint32_t* csr = dir ? csr_t : csr_s;
    const __half* x = hb + (size_t)(dir * 4 + h - 1) * CAPO;
    __half* next = hb + (size_t)(dir * 4 + h) * CAPO;

    int lane    = threadIdx.x & 31;
    int pairIdx = lane >> 4;        // 0: even edges, 1: odd edges
    int hlane   = lane & 15;
    int node = (int)((blockIdx.x * blockDim.x + threadIdx.x) >> 5);
    if (node >= n) return;

    int beg = rowptr[node];
    int end = rowptr[node + 1];

    float acc[4] = {0.f, 0.f, 0.f, 0.f};
    const uint2* xb = (const uint2*)x + hlane;   // row stride = 16 uint2 (64 halves)

    for (int p = beg; p < end; p += 32) {
        int cnt = end - p;
        if (cnt > 32) cnt = 32;
        uint32_t pk = 0;
        if (lane < cnt) {
            asm volatile("ld.global.cs.u32 %0, [%1];" : "=r"(pk) : "l"(csr + p + lane));
        }
        #pragma unroll
        for (int j = 0; j < 32; j += 2) {
            int je = j + pairIdx;
            uint32_t pe = __shfl_sync(0xffffffffu, pk, je);
            if (je < cnt) {
                int   c  = (int)(pe >> 15);
                float wv = (float)(pe & 0x7FFFu) * W_INV;
                uint2 raw = __ldg(xb + (size_t)c * 16);
                float2 v0 = __half22float2(*(__half2*)&raw.x);
                float2 v1 = __half22float2(*(__half2*)&raw.y);
                acc[0] = fmaf(wv, v0.x, acc[0]);
                acc[1] = fmaf(wv, v0.y, acc[1]);
                acc[2] = fmaf(wv, v1.x, acc[2]);
                acc[3] = fmaf(wv, v1.y, acc[3]);
            }
        }
    }

    // combine the two half-warps' partial sums
    #pragma unroll
    for (int i = 0; i < 4; i++)
        acc[i] += __shfl_xor_sync(0xffffffffu, acc[i], 16);

    if (pairIdx == 0) {
        __half2 o[2];
        o[0] = __floats2half2_rn(acc[0], acc[1]);
        o[1] = __floats2half2_rn(acc[2], acc[3]);
        *((uint2*)(next + (size_t)node * NOUT) + hlane) = *(uint2*)o;
    }
}

// ======================= tensor-core helpers ========================
__device__ __forceinline__ uint32_t smem_u32(const void* p) {
    return (uint32_t)__cvta_generic_to_shared(p);
}
__device__ __forceinline__ void ldsm_x4(uint32_t* r, uint32_t addr) {
    asm volatile("ldmatrix.sync.aligned.m8n8.x4.shared.b16 {%0,%1,%2,%3}, [%4];"
                 : "=r"(r[0]), "=r"(r[1]), "=r"(r[2]), "=r"(r[3]) : "r"(addr));
}
__device__ __forceinline__ void ldsm_x4_t(uint32_t* r, uint32_t addr) {
    asm volatile("ldmatrix.sync.aligned.m8n8.x4.trans.shared.b16 {%0,%1,%2,%3}, [%4];"
                 : "=r"(r[0]), "=r"(r[1]), "=r"(r[2]), "=r"(r[3]) : "r"(addr));
}
__device__ __forceinline__ void mma16816(float* c, const uint32_t* a,
                                         uint32_t b0, uint32_t b1) {
    asm volatile("mma.sync.aligned.m16n8k16.row.col.f32.f16.f16.f32 "
                 "{%0,%1,%2,%3}, {%4,%5,%6,%7}, {%8,%9}, {%0,%1,%2,%3};"
                 : "+f"(c[0]), "+f"(c[1]), "+f"(c[2]), "+f"(c[3])
                 : "r"(a[0]), "r"(a[1]), "r"(a[2]), "r"(a[3]), "r"(b0), "r"(b1));
}

#define A_STRIDE 40   // halves per row (32 + 8 pad)
#define W2_STRIDE 72  // halves per row (64 + 8 pad)

// ======================= input GEMM: y0 = A @ Wc + bc (fp16 out, 64 cols) ===
__global__ __launch_bounds__(256)
void gemm_input2_mma(const float* __restrict__ A0, const float* __restrict__ A1,
                     const float* __restrict__ wc, const float* __restrict__ bc,
                     __half* __restrict__ hb, int M) {
    const float* A  = blockIdx.y ? A1 : A0;
    const float* Wc = wc + (size_t)blockIdx.y * FEAT * NOUT;
    const float* Bc = bc + blockIdx.y * NOUT;
    __half* y = hb + (size_t)(blockIdx.y * 4) * CAPO;

    __shared__ __half Ah[128 * A_STRIDE];
    __shared__ __half Wh[32 * W2_STRIDE];
    int tid = threadIdx.x;
    int lane = tid & 31;
    int warp = tid >> 5;
    int wm = warp >> 1;
    int wn = warp & 1;
    int row0 = blockIdx.x * 128;

    float acc[2][4][4];
    #pragma unroll
    for (int i = 0; i < 2; i++)
        #pragma unroll
        for (int j = 0; j < 4; j++)
            #pragma unroll
            for (int k = 0; k < 4; k++) acc[i][j][k] = 0.f;

    for (int k0 = 0; k0 < FEAT; k0 += 32) {
        #pragma unroll
        for (int i = 0; i < 4; i++) {
            int f = tid + i * 256;
            int r = f >> 3;
            int cg = (f & 7) * 4;
            float4 v = make_float4(0.f, 0.f, 0.f, 0.f);
            if (row0 + r < M)
                v = *(const float4*)(A + (size_t)(row0 + r) * FEAT + k0 + cg);
            __half2 h0 = __floats2half2_rn(v.x, v.y);
            __half2 h1 = __floats2half2_rn(v.z, v.w);
            *(uint2*)&Ah[r * A_STRIDE + cg] = make_uint2(*(uint32_t*)&h0, *(uint32_t*)&h1);
        }
        #pragma unroll
        for (int i = 0; i < 2; i++) {
            int f = tid + i * 256;
            int r = f >> 4;
            int cg = (f & 15) * 4;
            float4 v = *(const float4*)(Wc + (size_t)(k0 + r) * NOUT + cg);
            __half2 h0 = __floats2half2_rn(v.x, v.y);
            __half2 h1 = __floats2half2_rn(v.z, v.w);
            *(uint2*)&Wh[r * W2_STRIDE + cg] = make_uint2(*(uint32_t*)&h0, *(uint32_t*)&h1);
        }
        __syncthreads();

        #pragma unroll
        for (int ks = 0; ks < 32; ks += 16) {
            uint32_t aF[2][4];
            #pragma unroll
            for (int mt = 0; mt < 2; mt++) {
                int r = wm * 32 + mt * 16 + (lane & 15);
                int c = ks + ((lane >> 4) << 3);
                ldsm_x4(aF[mt], smem_u32(&Ah[r * A_STRIDE + c]));
            }
            uint32_t bF[2][4];
            #pragma unroll
            for (int ng = 0; ng < 2; ng++) {
                int r = ks + ((lane >> 4) << 3) + (lane & 7);
                int c = wn * 32 + ng * 16 + (((lane >> 3) & 1) << 3);
                ldsm_x4_t(bF[ng], smem_u32(&Wh[r * W2_STRIDE + c]));
            }
            #pragma unroll
            for (int mt = 0; mt < 2; mt++)
                #pragma unroll
                for (int nt = 0; nt < 4; nt++) {
                    int ng = nt >> 1, sel = nt & 1;
                    mma16816(acc[mt][nt], aF[mt], bF[ng][sel], bF[ng][sel + 2]);
                }
        }
        __syncthreads();
    }

    #pragma unroll
    for (int mt = 0; mt < 2; mt++) {
        int r_ = row0 + wm * 32 + mt * 16 + (lane >> 2);
        #pragma unroll
        for (int nt = 0; nt < 4; nt++) {
            int c_ = wn * 32 + nt * 8 + (lane & 3) * 2;
            float b0 = __ldg(Bc + c_);
            float b1 = __ldg(Bc + c_ + 1);
            if (r_ < M) {
                __half2 hv = __floats2half2_rn(acc[mt][nt][0] + b0, acc[mt][nt][1] + b1);
                *(__half2*)(y + (size_t)r_ * NOUT + c_) = hv;
            }
            if (r_ + 8 < M) {
                __half2 hv = __floats2half2_rn(acc[mt][nt][2] + b0, acc[mt][nt][3] + b1);
                *(__half2*)(y + (size_t)(r_ + 8) * NOUT + c_) = hv;
            }
        }
    }
}

// ======================= final combine: out = b + Σ w_h * y_h ===============
__global__ __launch_bounds__(256)
void combine_kernel(const __half* __restrict__ hb,
                    const float* __restrict__ w_s, const float* __restrict__ w_t,
                    const float* __restrict__ bn, float* __restrict__ out, int M) {
    int i = blockIdx.x * blockDim.x + threadIdx.x;   // per 4 outputs
    int total = M * (NOUT / 4);
    if (i >= total) return;
    int col = (i * 4) & (NOUT - 1);
    float4 b = *(const float4*)(bn + col);
    float a0 = b.x, a1 = b.y, a2 = b.z, a3 = b.w;

    float wv[8];
    #pragma unroll
    for (int h = 0; h < 4; h++) {
        wv[h]     = __ldg(w_s + h);
        wv[4 + h] = __ldg(w_t + h);
    }
    #pragma unroll
    for (int k = 0; k < 8; k++) {
        uint2 raw = *((const uint2*)(hb + (size_t)k * CAPO) + i);
        float2 v0 = __half22float2(*(__half2*)&raw.x);
        float2 v1 = __half22float2(*(__half2*)&raw.y);
        float w = wv[k];
        a0 = fmaf(w, v0.x, a0);
        a1 = fmaf(w, v0.y, a1);
        a2 = fmaf(w, v1.x, a2);
        a3 = fmaf(w, v1.y, a3);
    }
    ((float4*)out)[i] = make_float4(a0, a1, a2, a3);
}

// ===========================================================================
extern "C" void kernel_launch(void* const* d_in, const int* in_sizes, int n_in,
                              void* d_out, int out_size) {
    const float* fsrc  = (const float*)d_in[0];
    const float* ftgt  = (const float*)d_in[1];
    const int*   erow  = (const int*)d_in[2];
    const int*   ecol  = (const int*)d_in[3];
    const float* ew    = (const float*)d_in[4];
    const float* W_src = (const float*)d_in[5];
    const float* b_src = (const float*)d_in[6];
    const float* W_tgt = (const float*)d_in[7];
    const float* b_tgt = (const float*)d_in[8];
    const float* w_s   = (const float*)d_in[9];
    const float* w_t   = (const float*)d_in[10];
    const float* W_nd  = (const float*)d_in[11];
    const float* b_nd  = (const float*)d_in[12];
    float* out = (float*)d_out;

    int M = in_sizes[0] / FEAT;
    int E = in_sizes[2];

    __half*   hb;     cudaGetSymbolAddress((void**)&hb, g_hbuf);
    int*      deg;    cudaGetSymbolAddress((void**)&deg, g_deg);
    int*      rowptr; cudaGetSymbolAddress((void**)&rowptr, g_rowptr);
    int*      fill;   cudaGetSymbolAddress((void**)&fill, g_fill);
    int*      bsum;   cudaGetSymbolAddress((void**)&bsum, g_bsum);
    uint32_t* csr;    cudaGetSymbolAddress((void**)&csr, g_csr);
    float*    wc;     cudaGetSymbolAddress((void**)&wc, g_wc);
    float*    bc;     cudaGetSymbolAddress((void**)&bc, g_bc);

    int* deg_s = deg;            int* deg_t = deg + NN;
    int* rp_s  = rowptr;         int* rp_t  = rowptr + (NN + 1);
    int* fil_s = fill;           int* fil_t = fill + NN;
    int* bs_s  = bsum;           int* bs_t  = bsum + 128;
    uint32_t* csr_s = csr;       uint32_t* csr_t = csr + NEDGE;

    int eblocks = (E + 255) / 256;
    int nchunks = (M + 1023) / 1024;

    bool fork = (g_side != 0 && g_evFork != 0 && g_evJoin != 0);
    cudaStream_t cs = fork ? g_side : 0;

    if (fork) {
        cudaEventRecord(g_evFork, 0);
        cudaStreamWaitEvent(g_side, g_evFork, 0);
    }

    // ---- CSR build (side stream) ----
    cudaMemsetAsync(deg_s, 0, 2 * NN * sizeof(int), cs);
    hist_kernel<<<eblocks, 256, 0, cs>>>(erow, ecol, deg_s, deg_t, E);
    {
        dim3 g(nchunks, 2);
        scan_chunk2<<<g, 1024, 0, cs>>>(deg_s, rp_s, bs_s, deg_t, rp_t, bs_t, M);
    }
    {
        dim3 g((M + 256) / 256, 2);
        finalize2<<<g, 256, 0, cs>>>(rp_s, bs_s, fil_s, rp_t, bs_t, fil_t, M, nchunks, E);
    }
    scatter_kernel<<<eblocks, 256, 0, cs>>>(erow, ecol, ew, fil_s, fil_t, csr_s, csr_t, E);

    // ---- weight fold + input projections (main stream, overlap CSR) ----
    {
        dim3 g(FEAT + 1, 2);
        fold_kernel<<<g, 64>>>(W_src, b_src, W_tgt, b_tgt, W_nd, wc, bc);
    }
    {
        dim3 g((M + 127) / 128, 2);
        gemm_input2_mma<<<g, 256>>>(fsrc, ftgt, wc, bc, hb, M);
    }

    if (fork) {
        cudaEventRecord(g_evJoin, g_side);
        cudaStreamWaitEvent(0, g_evJoin, 0);
    }

    // ---- hops (64-dim; both directions per launch; warp per node) ----
    {
        dim3 g((M * 32 + 255) / 256, 2);
        for (int h = 1; h <= HOPS; h++)
            spmm2_kernel<<<g, 256>>>(rp_s, rp_t, csr_s, csr_t, hb, h, M);
    }

    // ---- final combine (elementwise, replaces output GEMM) ----
    {
        int total = M * (NOUT / 4);
        combine_kernel<<<(total + 255) / 256, 256>>>(hb, w_s, w_t, b_nd, out, M);
    }
}

// round 16
// speedup vs baseline: 1.1426x; 1.1426x over previous
#include <cuda_runtime.h>
#include <cuda_fp16.h>
#include <cstddef>
#include <cstdint>

#define NN    100000
#define NEDGE 3200000
#define FEAT  256
#define HID   128
#define NOUT  64
#define HOPS  3
#define CAPO  ((size_t)NN * NOUT)

#define W_SCALE 32767.0f
#define W_INV   (1.0f / 32767.0f)

// 8 fp16 hop buffers (64-dim): s-dir y0..y3, t-dir y0..y3
__device__ __half    g_hbuf[8][CAPO];
__device__ int       g_deg[2][NN];
__device__ int       g_rowptr[2][NN + 1];
__device__ int       g_fill[2][NN];
__device__ int       g_bsum[2][128];
__device__ uint32_t  g_csr[2][NEDGE];   // packed: (nbr << 15) | q15(weight)
__device__ float     g_wc[2][FEAT][NOUT];   // folded W_in @ Wn_half
__device__ float     g_bc[2][NOUT];         // folded b_in @ Wn_half
__device__ int       g_perm[2][NN];         // degree-sorted node order
__device__ int       g_dbin[2][256];        // degree histogram / fill

// side stream + events (host objects; created once at load)
static cudaStream_t g_side = 0;
static cudaEvent_t  g_evFork = 0, g_evJoin = 0, g_evHist = 0;
namespace {
struct StreamInit {
    StreamInit() {
        cudaStreamCreateWithFlags(&g_side, cudaStreamNonBlocking);
        cudaEventCreateWithFlags(&g_evFork, cudaEventDisableTiming);
        cudaEventCreateWithFlags(&g_evJoin, cudaEventDisableTiming);
        cudaEventCreateWithFlags(&g_evHist, cudaEventDisableTiming);
    }
};
static StreamInit g_streamInit;
}

// ======================= weight folding =======================
__global__ __launch_bounds__(64)
void fold_kernel(const float* __restrict__ W_src, const float* __restrict__ b_src,
                 const float* __restrict__ W_tgt, const float* __restrict__ b_tgt,
                 const float* __restrict__ Wn, float* __restrict__ wc,
                 float* __restrict__ bc) {
    int dir = blockIdx.y;
    int i = blockIdx.x;          // 0..FEAT; FEAT => bias row
    int j = threadIdx.x;         // 0..63
    const float* W = dir ? W_tgt : W_src;
    const float* b = dir ? b_tgt : b_src;
    float acc = 0.f;
    if (i < FEAT) {
        for (int k = 0; k < HID; k++)
            acc += W[i * HID + k] * Wn[(size_t)(dir * HID + k) * NOUT + j];
        wc[(size_t)dir * FEAT * NOUT + (size_t)i * NOUT + j] = acc;
    } else {
        for (int k = 0; k < HID; k++)
            acc += b[k] * Wn[(size_t)(dir * HID + k) * NOUT + j];
        bc[dir * NOUT + j] = acc;
    }
}

// ======================= CSR build =======================
__global__ __launch_bounds__(256)
void hist_kernel(const int* __restrict__ erow, const int* __restrict__ ecol,
                 int* __restrict__ deg_s, int* __restrict__ deg_t, int E) {
    int e = blockIdx.x * blockDim.x + threadIdx.x;
    if (e < E) {
        atomicAdd(&deg_s[erow[e]], 1);
        atomicAdd(&deg_t[ecol[e]], 1);
    }
}

__global__ __launch_bounds__(1024)
void scan_chunk2(const int* __restrict__ deg_s, int* __restrict__ rp_s, int* __restrict__ bs_s,
                 const int* __restrict__ deg_t, int* __restrict__ rp_t, int* __restrict__ bs_t,
                 int n) {
    const int* in = blockIdx.y ? deg_t : deg_s;
    int* out = blockIdx.y ? rp_t : rp_s;
    int* bsum = blockIdx.y ? bs_t : bs_s;
    __shared__ int sh[1024];
    int t = threadIdx.x;
    int g = blockIdx.x * 1024 + t;
    int v = (g < n) ? in[g] : 0;
    sh[t] = v;
    __syncthreads();
    #pragma unroll
    for (int off = 1; off < 1024; off <<= 1) {
        int x = (t >= off) ? sh[t - off] : 0;
        __syncthreads();
        sh[t] += x;
        __syncthreads();
    }
    if (g < n) out[g] = sh[t] - v;
    if (t == 1023) bsum[blockIdx.x] = sh[1023];
}

__global__ __launch_bounds__(256)
void finalize2(int* __restrict__ rp_s, const int* __restrict__ bs_s, int* __restrict__ fil_s,
               int* __restrict__ rp_t, const int* __restrict__ bs_t, int* __restrict__ fil_t,
               int n, int nchunks, int total) {
    int* rowptr = blockIdx.y ? rp_t : rp_s;
    const int* bs = blockIdx.y ? bs_t : bs_s;
    int* fill = blockIdx.y ? fil_t : fil_s;
    __shared__ int sh[128];
    int t = threadIdx.x;
    if (t < 128) sh[t] = (t < nchunks) ? bs[t] : 0;
    __syncthreads();
    #pragma unroll
    for (int off = 1; off < 128; off <<= 1) {
        int x = (t >= off && t < 128) ? sh[t - off] : 0;
        __syncthreads();
        if (t < 128) sh[t] += x;
        __syncthreads();
    }
    int chunk = (blockIdx.x * 256) >> 10;
    int pre = chunk ? sh[chunk - 1] : 0;
    int g = blockIdx.x * 256 + t;
    if (g < n) {
        int v = rowptr[g] + pre;
        rowptr[g] = v;
        fill[g] = v;
    }
    if (g == n) rowptr[n] = total;
}

__device__ __forceinline__ void stcs_u32(uint32_t* addr, uint32_t v) {
    asm volatile("st.global.cs.u32 [%0], %1;" :: "l"(addr), "r"(v) : "memory");
}

__global__ __launch_bounds__(256)
void scatter_kernel(const int* __restrict__ erow, const int* __restrict__ ecol,
                    const float* __restrict__ ew,
                    int* __restrict__ fill_s, int* __restrict__ fill_t,
                    uint32_t* __restrict__ csr_s, uint32_t* __restrict__ csr_t, int E) {
    int e = blockIdx.x * blockDim.x + threadIdx.x;
    if (e >= E) return;
    int r = erow[e];
    int c = ecol[e];
    uint32_t qw = (uint32_t)__float2int_rn(ew[e] * W_SCALE);
    int ps = atomicAdd(&fill_s[r], 1);
    stcs_u32(csr_s + ps, ((uint32_t)c << 15) | qw);
    int pt = atomicAdd(&fill_t[c], 1);
    stcs_u32(csr_t + pt, ((uint32_t)r << 15) | qw);
}

// ======================= degree-sorted permutation (counting sort) ==========
__global__ __launch_bounds__(256)
void dhist_kernel(const int* __restrict__ deg_s, const int* __restrict__ deg_t,
                  int* __restrict__ dbin, int n) {
    int dir = blockIdx.y;
    const int* deg = dir ? deg_t : deg_s;
    int i = blockIdx.x * blockDim.x + threadIdx.x;
    if (i < n) {
        int d = deg[i];
        if (d > 255) d = 255;
        atomicAdd(&dbin[dir * 256 + d], 1);
    }
}

// exclusive scan of 256 bins per dir (grid.x = 2)
__global__ __launch_bounds__(256)
void dscan_kernel(int* __restrict__ dbin) {
    int dir = blockIdx.x;
    __shared__ int sh[256];
    int t = threadIdx.x;
    int v = dbin[dir * 256 + t];
    sh[t] = v;
    __syncthreads();
    #pragma unroll
    for (int off = 1; off < 256; off <<= 1) {
        int x = (t >= off) ? sh[t - off] : 0;
        __syncthreads();
        sh[t] += x;
        __syncthreads();
    }
    dbin[dir * 256 + t] = sh[t] - v;   // exclusive
}

__global__ __launch_bounds__(256)
void dscatter_kernel(const int* __restrict__ deg_s, const int* __restrict__ deg_t,
                     int* __restrict__ dbin, int* __restrict__ perm, int n) {
    int dir = blockIdx.y;
    const int* deg = dir ? deg_t : deg_s;
    int i = blockIdx.x * blockDim.x + threadIdx.x;
    if (i < n) {
        int d = deg[i];
        if (d > 255) d = 255;
        int pos = atomicAdd(&dbin[dir * 256 + d], 1);
        perm[(size_t)dir * NN + pos] = i;
    }
}

// ======================= SPMM (64-dim fp16 gather, fp32 accumulate) =========
// HALF-WARP per node: 16 lanes x 8B = 128B row; 2 nodes per warp.
// Nodes taken in degree-sorted order via perm -> paired nodes have ~equal deg.
__global__ __launch_bounds__(256)
void spmm2_kernel(const int* __restrict__ rp_s, const int* __restrict__ rp_t,
                  const uint32_t* __restrict__ csr_s, const uint32_t* __restrict__ csr_t,
                  const int* __restrict__ perm,
                  __half* __restrict__ hb, int h, int n) {
    int dir = blockIdx.y;
    const int* rowptr = dir ? rp_t : rp_s;
    const uint32_t* csr = dir ? csr_t : csr_s;
    const int* pm = perm + (size_t)dir * NN;
    const __half* x = hb + (size_t)(dir * 4 + h - 1) * CAPO;
    __half* next = hb + (size_t)(dir * 4 + h) * CAPO;

    int lane  = threadIdx.x & 31;
    int half  = lane >> 4;
    int hlane = lane & 15;
    int pairw = (int)((blockIdx.x * blockDim.x + threadIdx.x) >> 5);
    int idx   = pairw * 2 + half;
    bool valid = (idx < n);
    int node = valid ? pm[idx] : 0;

    int beg = valid ? rowptr[node] : 0;
    int end = valid ? rowptr[node + 1] : 0;

    float acc[4] = {0.f, 0.f, 0.f, 0.f};
    const uint2* xb = (const uint2*)x + hlane;   // row stride = 16 uint2 (64 halves)

    int p = beg;
    while (true) {
        int cnt = end - p;
        if (cnt > 16) cnt = 16;
        unsigned any = __ballot_sync(0xffffffffu, cnt > 0);
        if (!any) break;
        uint32_t pk = 0;
        if (hlane < cnt) {
            asm volatile("ld.global.cs.u32 %0, [%1];" : "=r"(pk) : "l"(csr + p + hlane));
        }
        #pragma unroll
        for (int j = 0; j < 16; j++) {
            uint32_t pe = __shfl_sync(0xffffffffu, pk, (half << 4) + j);
            if (j < cnt) {
                int   c  = (int)(pe >> 15);
                float wv = (float)(pe & 0x7FFFu) * W_INV;
                uint2 raw = __ldg(xb + (size_t)c * 16);
                float2 v0 = __half22float2(*(__half2*)&raw.x);
                float2 v1 = __half22float2(*(__half2*)&raw.y);
                acc[0] = fmaf(wv, v0.x, acc[0]);
                acc[1] = fmaf(wv, v0.y, acc[1]);
                acc[2] = fmaf(wv, v1.x, acc[2]);
                acc[3] = fmaf(wv, v1.y, acc[3]);
            }
        }
        p += cnt;
    }

    if (valid) {
        __half2 o[2];
        o[0] = __floats2half2_rn(acc[0], acc[1]);
        o[1] = __floats2half2_rn(acc[2], acc[3]);
        *((uint2*)(next + (size_t)node * NOUT) + hlane) = *(uint2*)o;
    }
}

// ======================= tensor-core helpers ========================
__device__ __forceinline__ uint32_t smem_u32(const void* p) {
    return (uint32_t)__cvta_generic_to_shared(p);
}
__device__ __forceinline__ void ldsm_x4(uint32_t* r, uint32_t addr) {
    asm volatile("ldmatrix.sync.aligned.m8n8.x4.shared.b16 {%0,%1,%2,%3}, [%4];"
                 : "=r"(r[0]), "=r"(r[1]), "=r"(r[2]), "=r"(r[3]) : "r"(addr));
}
__device__ __forceinline__ void ldsm_x4_t(uint32_t* r, uint32_t addr) {
    asm volatile("ldmatrix.sync.aligned.m8n8.x4.trans.shared.b16 {%0,%1,%2,%3}, [%4];"
                 : "=r"(r[0]), "=r"(r[1]), "=r"(r[2]), "=r"(r[3]) : "r"(addr));
}
__device__ __forceinline__ void mma16816(float* c, const uint32_t* a,
                                         uint32_t b0, uint32_t b1) {
    asm volatile("mma.sync.aligned.m16n8k16.row.col.f32.f16.f16.f32 "
                 "{%0,%1,%2,%3}, {%4,%5,%6,%7}, {%8,%9}, {%0,%1,%2,%3};"
                 : "+f"(c[0]), "+f"(c[1]), "+f"(c[2]), "+f"(c[3])
                 : "r"(a[0]), "r"(a[1]), "r"(a[2]), "r"(a[3]), "r"(b0), "r"(b1));
}

#define A_STRIDE 40   // halves per row (32 + 8 pad)
#define W2_STRIDE 72  // halves per row (64 + 8 pad)

// ======================= input GEMM: y0 = A @ Wc + bc (fp16 out, 64 cols) ===
__global__ __launch_bounds__(256)
void gemm_input2_mma(const float* __restrict__ A0, const float* __restrict__ A1,
                     const float* __restrict__ wc, const float* __restrict__ bc,
                     __half* __restrict__ hb, int M) {
    const float* A  = blockIdx.y ? A1 : A0;
    const float* Wc = wc + (size_t)blockIdx.y * FEAT * NOUT;
    const float* Bc = bc + blockIdx.y * NOUT;
    __half* y = hb + (size_t)(blockIdx.y * 4) * CAPO;

    __shared__ __half Ah[128 * A_STRIDE];
    __shared__ __half Wh[32 * W2_STRIDE];
    int tid = threadIdx.x;
    int lane = tid & 31;
    int warp = tid >> 5;
    int wm = warp >> 1;
    int wn = warp & 1;
    int row0 = blockIdx.x * 128;

    float acc[2][4][4];
    #pragma unroll
    for (int i = 0; i < 2; i++)
        #pragma unroll
        for (int j = 0; j < 4; j++)
            #pragma unroll
            for (int k = 0; k < 4; k++) acc[i][j][k] = 0.f;

    for (int k0 = 0; k0 < FEAT; k0 += 32) {
        #pragma unroll
        for (int i = 0; i < 4; i++) {
            int f = tid + i * 256;
            int r = f >> 3;
            int cg = (f & 7) * 4;
            float4 v = make_float4(0.f, 0.f, 0.f, 0.f);
            if (row0 + r < M)
                v = *(const float4*)(A + (size_t)(row0 + r) * FEAT + k0 + cg);
            __half2 h0 = __floats2half2_rn(v.x, v.y);
            __half2 h1 = __floats2half2_rn(v.z, v.w);
            *(uint2*)&Ah[r * A_STRIDE + cg] = make_uint2(*(uint32_t*)&h0, *(uint32_t*)&h1);
        }
        #pragma unroll
        for (int i = 0; i < 2; i++) {
            int f = tid + i * 256;
            int r = f >> 4;
            int cg = (f & 15) * 4;
            float4 v = *(const float4*)(Wc + (size_t)(k0 + r) * NOUT + cg);
            __half2 h0 = __floats2half2_rn(v.x, v.y);
            __half2 h1 = __floats2half2_rn(v.z, v.w);
            *(uint2*)&Wh[r * W2_STRIDE + cg] = make_uint2(*(uint32_t*)&h0, *(uint32_t*)&h1);
        }
        __syncthreads();

        #pragma unroll
        for (int ks = 0; ks < 32; ks += 16) {
            uint32_t aF[2][4];
            #pragma unroll
            for (int mt = 0; mt < 2; mt++) {
                int r = wm * 32 + mt * 16 + (lane & 15);
                int c = ks + ((lane >> 4) << 3);
                ldsm_x4(aF[mt], smem_u32(&Ah[r * A_STRIDE + c]));
            }
            uint32_t bF[2][4];
            #pragma unroll
            for (int ng = 0; ng < 2; ng++) {
                int r = ks + ((lane >> 4) << 3) + (lane & 7);
                int c = wn * 32 + ng * 16 + (((lane >> 3) & 1) << 3);
                ldsm_x4_t(bF[ng], smem_u32(&Wh[r * W2_STRIDE + c]));
            }
            #pragma unroll
            for (int mt = 0; mt < 2; mt++)
                #pragma unroll
                for (int nt = 0; nt < 4; nt++) {
                    int ng = nt >> 1, sel = nt & 1;
                    mma16816(acc[mt][nt], aF[mt], bF[ng][sel], bF[ng][sel + 2]);
                }
        }
        __syncthreads();
    }

    #pragma unroll
    for (int mt = 0; mt < 2; mt++) {
        int r_ = row0 + wm * 32 + mt * 16 + (lane >> 2);
        #pragma unroll
        for (int nt = 0; nt < 4; nt++) {
            int c_ = wn * 32 + nt * 8 + (lane & 3) * 2;
            float b0 = __ldg(Bc + c_);
            float b1 = __ldg(Bc + c_ + 1);
            if (r_ < M) {
                __half2 hv = __floats2half2_rn(acc[mt][nt][0] + b0, acc[mt][nt][1] + b1);
                *(__half2*)(y + (size_t)r_ * NOUT + c_) = hv;
            }
            if (r_ + 8 < M) {
                __half2 hv = __floats2half2_rn(acc[mt][nt][2] + b0, acc[mt][nt][3] + b1);
                *(__half2*)(y + (size_t)(r_ + 8) * NOUT + c_) = hv;
            }
        }
    }
}

// ======================= final combine: out = b + Σ w_h * y_h ===============
__global__ __launch_bounds__(256)
void combine_kernel(const __half* __restrict__ hb,
                    const float* __restrict__ w_s, const float* __restrict__ w_t,
                    const float* __restrict__ bn, float* __restrict__ out, int M) {
    int i = blockIdx.x * blockDim.x + threadIdx.x;   // per 4 outputs
    int total = M * (NOUT / 4);
    if (i >= total) return;
    int col = (i * 4) & (NOUT - 1);
    float4 b = *(const float4*)(bn + col);
    float a0 = b.x, a1 = b.y, a2 = b.z, a3 = b.w;

    float wv[8];
    #pragma unroll
    for (int h = 0; h < 4; h++) {
        wv[h]     = __ldg(w_s + h);
        wv[4 + h] = __ldg(w_t + h);
    }
    #pragma unroll
    for (int k = 0; k < 8; k++) {
        uint2 raw = *((const uint2*)(hb + (size_t)k * CAPO) + i);
        float2 v0 = __half22float2(*(__half2*)&raw.x);
        float2 v1 = __half22float2(*(__half2*)&raw.y);
        float w = wv[k];
        a0 = fmaf(w, v0.x, a0);
        a1 = fmaf(w, v0.y, a1);
        a2 = fmaf(w, v1.x, a2);
        a3 = fmaf(w, v1.y, a3);
    }
    ((float4*)out)[i] = make_float4(a0, a1, a2, a3);
}

// ===========================================================================
extern "C" void kernel_launch(void* const* d_in, const int* in_sizes, int n_in,
                              void* d_out, int out_size) {
    const float* fsrc  = (const float*)d_in[0];
    const float* ftgt  = (const float*)d_in[1];
    const int*   erow  = (const int*)d_in[2];
    const int*   ecol  = (const int*)d_in[3];
    const float* ew    = (const float*)d_in[4];
    const float* W_src = (const float*)d_in[5];
    const float* b_src = (const float*)d_in[6];
    const float* W_tgt = (const float*)d_in[7];
    const float* b_tgt = (const float*)d_in[8];
    const float* w_s   = (const float*)d_in[9];
    const float* w_t   = (const float*)d_in[10];
    const float* W_nd  = (const float*)d_in[11];
    const float* b_nd  = (const float*)d_in[12];
    float* out = (float*)d_out;

    int M = in_sizes[0] / FEAT;
    int E = in_sizes[2];

    __half*   hb;     cudaGetSymbolAddress((void**)&hb, g_hbuf);
    int*      deg;    cudaGetSymbolAddress((void**)&deg, g_deg);
    int*      rowptr; cudaGetSymbolAddress((void**)&rowptr, g_rowptr);
    int*      fill;   cudaGetSymbolAddress((void**)&fill, g_fill);
    int*      bsum;   cudaGetSymbolAddress((void**)&bsum, g_bsum);
    uint32_t* csr;    cudaGetSymbolAddress((void**)&csr, g_csr);
    float*    wc;     cudaGetSymbolAddress((void**)&wc, g_wc);
    float*    bc;     cudaGetSymbolAddress((void**)&bc, g_bc);
    int*      perm;   cudaGetSymbolAddress((void**)&perm, g_perm);
    int*      dbin;   cudaGetSymbolAddress((void**)&dbin, g_dbin);

    int* deg_s = deg;            int* deg_t = deg + NN;
    int* rp_s  = rowptr;         int* rp_t  = rowptr + (NN + 1);
    int* fil_s = fill;           int* fil_t = fill + NN;
    int* bs_s  = bsum;           int* bs_t  = bsum + 128;
    uint32_t* csr_s = csr;       uint32_t* csr_t = csr + NEDGE;

    int eblocks = (E + 255) / 256;
    int nchunks = (M + 1023) / 1024;
    int nblocks = (M + 255) / 256;

    bool fork = (g_side != 0 && g_evFork != 0 && g_evJoin != 0 && g_evHist != 0);
    cudaStream_t cs = fork ? g_side : 0;

    if (fork) {
        cudaEventRecord(g_evFork, 0);
        cudaStreamWaitEvent(g_side, g_evFork, 0);
    }

    // ---- CSR build (side stream) ----
    cudaMemsetAsync(deg_s, 0, 2 * NN * sizeof(int), cs);
    hist_kernel<<<eblocks, 256, 0, cs>>>(erow, ecol, deg_s, deg_t, E);
    if (fork) cudaEventRecord(g_evHist, cs);   // degrees final here
    {
        dim3 g(nchunks, 2);
        scan_chunk2<<<g, 1024, 0, cs>>>(deg_s, rp_s, bs_s, deg_t, rp_t, bs_t, M);
    }
    {
        dim3 g((M + 256) / 256, 2);
        finalize2<<<g, 256, 0, cs>>>(rp_s, bs_s, fil_s, rp_t, bs_t, fil_t, M, nchunks, E);
    }
    scatter_kernel<<<eblocks, 256, 0, cs>>>(erow, ecol, ew, fil_s, fil_t, csr_s, csr_t, E);

    // ---- weight fold + input projections (main stream, overlap CSR) ----
    {
        dim3 g(FEAT + 1, 2);
        fold_kernel<<<g, 64>>>(W_src, b_src, W_tgt, b_tgt, W_nd, wc, bc);
    }
    {
        dim3 g((M + 127) / 128, 2);
        gemm_input2_mma<<<g, 256>>>(fsrc, ftgt, wc, bc, hb, M);
    }

    // ---- degree-sorted permutation (main stream, after hist is done) ----
    if (fork) cudaStreamWaitEvent(0, g_evHist, 0);
    cudaMemsetAsync(dbin, 0, 2 * 256 * sizeof(int), 0);
    {
        dim3 g(nblocks, 2);
        dhist_kernel<<<g, 256>>>(deg_s, deg_t, dbin, M);
    }
    dscan_kernel<<<2, 256>>>(dbin);
    {
        dim3 g(nblocks, 2);
        dscatter_kernel<<<g, 256>>>(deg_s, deg_t, dbin, perm, M);
    }

    if (fork) {
        cudaEventRecord(g_evJoin, g_side);
        cudaStreamWaitEvent(0, g_evJoin, 0);
    }

    // ---- hops (64-dim; both directions per launch; 2 nodes per warp) ----
    {
        int warps = (M + 1) / 2;
        dim3 g((warps * 32 + 255) / 256, 2);
        for (int h = 1; h <= HOPS; h++)
            spmm2_kernel<<<g, 256>>>(rp_s, rp_t, csr_s, csr_t, perm, hb, h, M);
    }

    // ---- final combine (elementwise, replaces output GEMM) ----
    {
        int total = M * (NOUT / 4);
        combine_kernel<<<(total + 255) / 256, 256>>>(hb, w_s, w_t, b_nd, out, M);
    }
}

// round 17
// speedup vs baseline: 1.1672x; 1.0215x over previous
#include <cuda_runtime.h>
#include <cuda_fp16.h>
#include <cstddef>
#include <cstdint>

#define NN    100000
#define NEDGE 3200000
#define FEAT  256
#define HID   128
#define NOUT  64
#define HOPS  3
#define CAPO  ((size_t)NN * NOUT)

#define W_SCALE 32767.0f
#define W_INV   (1.0f / 32767.0f)

// 8 fp16 hop buffers (64-dim): s-dir y0..y3, t-dir y0..y3
__device__ __half    g_hbuf[8][CAPO];
__device__ int       g_deg[2][NN];
__device__ int       g_rowptr[2][NN + 1];
__device__ int       g_fill[2][NN];
__device__ int       g_bsum[2][128];
__device__ uint32_t  g_csr[2][NEDGE];   // packed: (nbr << 15) | q15(weight)
__device__ float     g_wc[2][FEAT][NOUT];   // folded W_in @ Wn_half
__device__ float     g_bc[2][NOUT];         // folded b_in @ Wn_half

// side stream + events (host objects; created once at load)
static cudaStream_t g_side = 0;
static cudaEvent_t  g_evFork = 0, g_evGemm = 0, g_evS = 0;
namespace {
struct StreamInit {
    StreamInit() {
        cudaStreamCreateWithFlags(&g_side, cudaStreamNonBlocking);
        cudaEventCreateWithFlags(&g_evFork, cudaEventDisableTiming);
        cudaEventCreateWithFlags(&g_evGemm, cudaEventDisableTiming);
        cudaEventCreateWithFlags(&g_evS, cudaEventDisableTiming);
    }
};
static StreamInit g_streamInit;
}

// ======================= weight folding =======================
__global__ __launch_bounds__(64)
void fold_kernel(const float* __restrict__ W_src, const float* __restrict__ b_src,
                 const float* __restrict__ W_tgt, const float* __restrict__ b_tgt,
                 const float* __restrict__ Wn, float* __restrict__ wc,
                 float* __restrict__ bc) {
    int dir = blockIdx.y;
    int i = blockIdx.x;          // 0..FEAT; FEAT => bias row
    int j = threadIdx.x;         // 0..63
    const float* W = dir ? W_tgt : W_src;
    const float* b = dir ? b_tgt : b_src;
    float acc = 0.f;
    if (i < FEAT) {
        for (int k = 0; k < HID; k++)
            acc += W[i * HID + k] * Wn[(size_t)(dir * HID + k) * NOUT + j];
        wc[(size_t)dir * FEAT * NOUT + (size_t)i * NOUT + j] = acc;
    } else {
        for (int k = 0; k < HID; k++)
            acc += b[k] * Wn[(size_t)(dir * HID + k) * NOUT + j];
        bc[dir * NOUT + j] = acc;
    }
}

// ======================= CSR build (single direction) =======================
__global__ __launch_bounds__(256)
void hist1_kernel(const int* __restrict__ enode, int* __restrict__ deg, int E) {
    int e = blockIdx.x * blockDim.x + threadIdx.x;
    if (e < E) atomicAdd(&deg[enode[e]], 1);
}

__global__ __launch_bounds__(1024)
void scan_chunk1(const int* __restrict__ in, int* __restrict__ out,
                 int* __restrict__ bsum, int n) {
    __shared__ int sh[1024];
    int t = threadIdx.x;
    int g = blockIdx.x * 1024 + t;
    int v = (g < n) ? in[g] : 0;
    sh[t] = v;
    __syncthreads();
    #pragma unroll
    for (int off = 1; off < 1024; off <<= 1) {
        int x = (t >= off) ? sh[t - off] : 0;
        __syncthreads();
        sh[t] += x;
        __syncthreads();
    }
    if (g < n) out[g] = sh[t] - v;
    if (t == 1023) bsum[blockIdx.x] = sh[1023];
}

__global__ __launch_bounds__(256)
void finalize1(int* __restrict__ rowptr, const int* __restrict__ bs,
               int* __restrict__ fill, int n, int nchunks, int total) {
    __shared__ int sh[128];
    int t = threadIdx.x;
    if (t < 128) sh[t] = (t < nchunks) ? bs[t] : 0;
    __syncthreads();
    #pragma unroll
    for (int off = 1; off < 128; off <<= 1) {
        int x = (t >= off && t < 128) ? sh[t - off] : 0;
        __syncthreads();
        if (t < 128) sh[t] += x;
        __syncthreads();
    }
    int chunk = (blockIdx.x * 256) >> 10;
    int pre = chunk ? sh[chunk - 1] : 0;
    int g = blockIdx.x * 256 + t;
    if (g < n) {
        int v = rowptr[g] + pre;
        rowptr[g] = v;
        fill[g] = v;
    }
    if (g == n) rowptr[n] = total;
}

__device__ __forceinline__ void stcs_u32(uint32_t* addr, uint32_t v) {
    asm volatile("st.global.cs.u32 [%0], %1;" :: "l"(addr), "r"(v) : "memory");
}

__global__ __launch_bounds__(256)
void scatter1_kernel(const int* __restrict__ enode, const int* __restrict__ enbr,
                     const float* __restrict__ ew,
                     int* __restrict__ fill, uint32_t* __restrict__ csr, int E) {
    int e = blockIdx.x * blockDim.x + threadIdx.x;
    if (e >= E) return;
    int nd = enode[e];
    int nb = enbr[e];
    uint32_t qw = (uint32_t)__float2int_rn(ew[e] * W_SCALE);
    int p = atomicAdd(&fill[nd], 1);
    stcs_u32(csr + p, ((uint32_t)nb << 15) | qw);
}

// ======================= SPMM (64-dim fp16 gather, fp32 accumulate) =========
// HALF-WARP per node: 16 lanes x 8B = 128B row; 2 nodes per warp. (R13 body)
__global__ __launch_bounds__(256)
void spmm1_kernel(const int* __restrict__ rowptr, const uint32_t* __restrict__ csr,
                  const __half* __restrict__ x, __half* __restrict__ next, int n) {
    int lane  = threadIdx.x & 31;
    int half  = lane >> 4;
    int hlane = lane & 15;
    int pairw = (int)((blockIdx.x * blockDim.x + threadIdx.x) >> 5);
    int node  = pairw * 2 + half;
    bool valid = (node < n);

    int beg = valid ? rowptr[node] : 0;
    int end = valid ? rowptr[node + 1] : 0;

    float acc[4] = {0.f, 0.f, 0.f, 0.f};
    const uint2* xb = (const uint2*)x + hlane;   // row stride = 16 uint2 (64 halves)

    int p = beg;
    while (true) {
        int cnt = end - p;
        if (cnt > 16) cnt = 16;
        unsigned any = __ballot_sync(0xffffffffu, cnt > 0);
        if (!any) break;
        uint32_t pk = 0;
        if (hlane < cnt) {
            asm volatile("ld.global.cs.u32 %0, [%1];" : "=r"(pk) : "l"(csr + p + hlane));
        }
        #pragma unroll
        for (int j = 0; j < 16; j++) {
            uint32_t pe = __shfl_sync(0xffffffffu, pk, (half << 4) + j);
            if (j < cnt) {
                int   c  = (int)(pe >> 15);
                float wv = (float)(pe & 0x7FFFu) * W_INV;
                uint2 raw = __ldg(xb + (size_t)c * 16);
                float2 v0 = __half22float2(*(__half2*)&raw.x);
                float2 v1 = __half22float2(*(__half2*)&raw.y);
                acc[0] = fmaf(wv, v0.x, acc[0]);
                acc[1] = fmaf(wv, v0.y, acc[1]);
                acc[2] = fmaf(wv, v1.x, acc[2]);
                acc[3] = fmaf(wv, v1.y, acc[3]);
            }
        }
        p += cnt;
    }

    if (valid) {
        __half2 o[2];
        o[0] = __floats2half2_rn(acc[0], acc[1]);
        o[1] = __floats2half2_rn(acc[2], acc[3]);
        *((uint2*)(next + (size_t)node * NOUT) + hlane) = *(uint2*)o;
    }
}

// ======================= tensor-core helpers ========================
__device__ __forceinline__ uint32_t smem_u32(const void* p) {
    return (uint32_t)__cvta_generic_to_shared(p);
}
__device__ __forceinline__ void ldsm_x4(uint32_t* r, uint32_t addr) {
    asm volatile("ldmatrix.sync.aligned.m8n8.x4.shared.b16 {%0,%1,%2,%3}, [%4];"
                 : "=r"(r[0]), "=r"(r[1]), "=r"(r[2]), "=r"(r[3]) : "r"(addr));
}
__device__ __forceinline__ void ldsm_x4_t(uint32_t* r, uint32_t addr) {
    asm volatile("ldmatrix.sync.aligned.m8n8.x4.trans.shared.b16 {%0,%1,%2,%3}, [%4];"
                 : "=r"(r[0]), "=r"(r[1]), "=r"(r[2]), "=r"(r[3]) : "r"(addr));
}
__device__ __forceinline__ void mma16816(float* c, const uint32_t* a,
                                         uint32_t b0, uint32_t b1) {
    asm volatile("mma.sync.aligned.m16n8k16.row.col.f32.f16.f16.f32 "
                 "{%0,%1,%2,%3}, {%4,%5,%6,%7}, {%8,%9}, {%0,%1,%2,%3};"
                 : "+f"(c[0]), "+f"(c[1]), "+f"(c[2]), "+f"(c[3])
                 : "r"(a[0]), "r"(a[1]), "r"(a[2]), "r"(a[3]), "r"(b0), "r"(b1));
}

#define A_STRIDE 40   // halves per row (32 + 8 pad)
#define W2_STRIDE 72  // halves per row (64 + 8 pad)

// ======================= input GEMM: y0 = A @ Wc + bc (fp16 out, 64 cols) ===
__global__ __launch_bounds__(256)
void gemm_input2_mma(const float* __restrict__ A0, const float* __restrict__ A1,
                     const float* __restrict__ wc, const float* __restrict__ bc,
                     __half* __restrict__ hb, int M) {
    const float* A  = blockIdx.y ? A1 : A0;
    const float* Wc = wc + (size_t)blockIdx.y * FEAT * NOUT;
    const float* Bc = bc + blockIdx.y * NOUT;
    __half* y = hb + (size_t)(blockIdx.y * 4) * CAPO;

    __shared__ __half Ah[128 * A_STRIDE];
    __shared__ __half Wh[32 * W2_STRIDE];
    int tid = threadIdx.x;
    int lane = tid & 31;
    int warp = tid >> 5;
    int wm = warp >> 1;
    int wn = warp & 1;
    int row0 = blockIdx.x * 128;

    float acc[2][4][4];
    #pragma unroll
    for (int i = 0; i < 2; i++)
        #pragma unroll
        for (int j = 0; j < 4; j++)
            #pragma unroll
            for (int k = 0; k < 4; k++) acc[i][j][k] = 0.f;

    for (int k0 = 0; k0 < FEAT; k0 += 32) {
        #pragma unroll
        for (int i = 0; i < 4; i++) {
            int f = tid + i * 256;
            int r = f >> 3;
            int cg = (f & 7) * 4;
            float4 v = make_float4(0.f, 0.f, 0.f, 0.f);
            if (row0 + r < M)
                v = *(const float4*)(A + (size_t)(row0 + r) * FEAT + k0 + cg);
            __half2 h0 = __floats2half2_rn(v.x, v.y);
            __half2 h1 = __floats2half2_rn(v.z, v.w);
            *(uint2*)&Ah[r * A_STRIDE + cg] = make_uint2(*(uint32_t*)&h0, *(uint32_t*)&h1);
        }
        #pragma unroll
        for (int i = 0; i < 2; i++) {
            int f = tid + i * 256;
            int r = f >> 4;
            int cg = (f & 15) * 4;
            float4 v = *(const float4*)(Wc + (size_t)(k0 + r) * NOUT + cg);
            __half2 h0 = __floats2half2_rn(v.x, v.y);
            __half2 h1 = __floats2half2_rn(v.z, v.w);
            *(uint2*)&Wh[r * W2_STRIDE + cg] = make_uint2(*(uint32_t*)&h0, *(uint32_t*)&h1);
        }
        __syncthreads();

        #pragma unroll
        for (int ks = 0; ks < 32; ks += 16) {
            uint32_t aF[2][4];
            #pragma unroll
            for (int mt = 0; mt < 2; mt++) {
                int r = wm * 32 + mt * 16 + (lane & 15);
                int c = ks + ((lane >> 4) << 3);
                ldsm_x4(aF[mt], smem_u32(&Ah[r * A_STRIDE + c]));
            }
            uint32_t bF[2][4];
            #pragma unroll
            for (int ng = 0; ng < 2; ng++) {
                int r = ks + ((lane >> 4) << 3) + (lane & 7);
                int c = wn * 32 + ng * 16 + (((lane >> 3) & 1) << 3);
                ldsm_x4_t(bF[ng], smem_u32(&Wh[r * W2_STRIDE + c]));
            }
            #pragma unroll
            for (int mt = 0; mt < 2; mt++)
                #pragma unroll
                for (int nt = 0; nt < 4; nt++) {
                    int ng = nt >> 1, sel = nt & 1;
                    mma16816(acc[mt][nt], aF[mt], bF[ng][sel], bF[ng][sel + 2]);
                }
        }
        __syncthreads();
    }

    #pragma unroll
    for (int mt = 0; mt < 2; mt++) {
        int r_ = row0 + wm * 32 + mt * 16 + (lane >> 2);
        #pragma unroll
        for (int nt = 0; nt < 4; nt++) {
            int c_ = wn * 32 + nt * 8 + (lane & 3) * 2;
            float b0 = __ldg(Bc + c_);
            float b1 = __ldg(Bc + c_ + 1);
            if (r_ < M) {
                __half2 hv = __floats2half2_rn(acc[mt][nt][0] + b0, acc[mt][nt][1] + b1);
                *(__half2*)(y + (size_t)r_ * NOUT + c_) = hv;
            }
            if (r_ + 8 < M) {
                __half2 hv = __floats2half2_rn(acc[mt][nt][2] + b0, acc[mt][nt][3] + b1);
                *(__half2*)(y + (size_t)(r_ + 8) * NOUT + c_) = hv;
            }
        }
    }
}

// ======================= final combine: out = b + Σ w_h * y_h ===============
__global__ __launch_bounds__(256)
void combine_kernel(const __half* __restrict__ hb,
                    const float* __restrict__ w_s, const float* __restrict__ w_t,
                    const float* __restrict__ bn, float* __restrict__ out, int M) {
    int i = blockIdx.x * blockDim.x + threadIdx.x;   // per 4 outputs
    int total = M * (NOUT / 4);
    if (i >= total) return;
    int col = (i * 4) & (NOUT - 1);
    float4 b = *(const float4*)(bn + col);
    float a0 = b.x, a1 = b.y, a2 = b.z, a3 = b.w;

    float wv[8];
    #pragma unroll
    for (int h = 0; h < 4; h++) {
        wv[h]     = __ldg(w_s + h);
        wv[4 + h] = __ldg(w_t + h);
    }
    #pragma unroll
    for (int k = 0; k < 8; k++) {
        uint2 raw = *((const uint2*)(hb + (size_t)k * CAPO) + i);
        float2 v0 = __half22float2(*(__half2*)&raw.x);
        float2 v1 = __half22float2(*(__half2*)&raw.y);
        float w = wv[k];
        a0 = fmaf(w, v0.x, a0);
        a1 = fmaf(w, v0.y, a1);
        a2 = fmaf(w, v1.x, a2);
        a3 = fmaf(w, v1.y, a3);
    }
    ((float4*)out)[i] = make_float4(a0, a1, a2, a3);
}

// ===========================================================================
extern "C" void kernel_launch(void* const* d_in, const int* in_sizes, int n_in,
                              void* d_out, int out_size) {
    const float* fsrc  = (const float*)d_in[0];
    const float* ftgt  = (const float*)d_in[1];
    const int*   erow  = (const int*)d_in[2];
    const int*   ecol  = (const int*)d_in[3];
    const float* ew    = (const float*)d_in[4];
    const float* W_src = (const float*)d_in[5];
    const float* b_src = (const float*)d_in[6];
    const float* W_tgt = (const float*)d_in[7];
    const float* b_tgt = (const float*)d_in[8];
    const float* w_s   = (const float*)d_in[9];
    const float* w_t   = (const float*)d_in[10];
    const float* W_nd  = (const float*)d_in[11];
    const float* b_nd  = (const float*)d_in[12];
    float* out = (float*)d_out;

    int M = in_sizes[0] / FEAT;
    int E = in_sizes[2];

    __half*   hb;     cudaGetSymbolAddress((void**)&hb, g_hbuf);
    int*      deg;    cudaGetSymbolAddress((void**)&deg, g_deg);
    int*      rowptr; cudaGetSymbolAddress((void**)&rowptr, g_rowptr);
    int*      fill;   cudaGetSymbolAddress((void**)&fill, g_fill);
    int*      bsum;   cudaGetSymbolAddress((void**)&bsum, g_bsum);
    uint32_t* csr;    cudaGetSymbolAddress((void**)&csr, g_csr);
    float*    wc;     cudaGetSymbolAddress((void**)&wc, g_wc);
    float*    bc;     cudaGetSymbolAddress((void**)&bc, g_bc);

    int* deg_s = deg;            int* deg_t = deg + NN;
    int* rp_s  = rowptr;         int* rp_t  = rowptr + (NN + 1);
    int* fil_s = fill;           int* fil_t = fill + NN;
    int* bs_s  = bsum;           int* bs_t  = bsum + 128;
    uint32_t* csr_s = csr;       uint32_t* csr_t = csr + NEDGE;

    int eblocks  = (E + 255) / 256;
    int nchunks  = (M + 1023) / 1024;
    int fblocks  = (M + 256) / 256;
    int warps    = (M + 1) / 2;
    int sblocks  = (warps * 32 + 255) / 256;

    bool fork = (g_side != 0 && g_evFork != 0 && g_evGemm != 0 && g_evS != 0);
    cudaStream_t cs = fork ? g_side : 0;   // s-direction chain stream

    if (fork) {
        cudaEventRecord(g_evFork, 0);
        cudaStreamWaitEvent(g_side, g_evFork, 0);
    }

    // ---- side stream: CSR_s build (overlaps fold+GEMM on main) ----
    cudaMemsetAsync(deg_s, 0, NN * sizeof(int), cs);
    hist1_kernel<<<eblocks, 256, 0, cs>>>(erow, deg_s, E);
    scan_chunk1<<<nchunks, 1024, 0, cs>>>(deg_s, rp_s, bs_s, M);
    finalize1<<<fblocks, 256, 0, cs>>>(rp_s, bs_s, fil_s, M, nchunks, E);
    scatter1_kernel<<<eblocks, 256, 0, cs>>>(erow, ecol, ew, fil_s, csr_s, E);

    // ---- main stream: deg_t memset + fold + GEMM (both dirs) ----
    cudaMemsetAsync(deg_t, 0, NN * sizeof(int), 0);
    {
        dim3 g(FEAT + 1, 2);
        fold_kernel<<<g, 64>>>(W_src, b_src, W_tgt, b_tgt, W_nd, wc, bc);
    }
    {
        dim3 g((M + 127) / 128, 2);
        gemm_input2_mma<<<g, 256>>>(fsrc, ftgt, wc, bc, hb, M);
    }
    if (fork) cudaEventRecord(g_evGemm, 0);

    // ---- side stream: s-direction hops (need CSR_s + GEMM's y0_s) ----
    if (fork) cudaStreamWaitEvent(g_side, g_evGemm, 0);
    for (int h = 1; h <= HOPS; h++)
        spmm1_kernel<<<sblocks, 256, 0, cs>>>(rp_s, csr_s,
                                              hb + (size_t)(h - 1) * CAPO,
                                              hb + (size_t)h * CAPO, M);
    if (fork) cudaEventRecord(g_evS, g_side);

    // ---- main stream: CSR_t build + t-direction hops ----
    hist1_kernel<<<eblocks, 256>>>(ecol, deg_t, E);
    scan_chunk1<<<nchunks, 1024>>>(deg_t, rp_t, bs_t, M);
    finalize1<<<fblocks, 256>>>(rp_t, bs_t, fil_t, M, nchunks, E);
    scatter1_kernel<<<eblocks, 256>>>(ecol, erow, ew, fil_t, csr_t, E);
    for (int h = 1; h <= HOPS; h++)
        spmm1_kernel<<<sblocks, 256>>>(rp_t, csr_t,
                                       hb + (size_t)(4 + h - 1) * CAPO,
                                       hb + (size_t)(4 + h) * CAPO, M);

    // ---- join + final combine ----
    if (fork) cudaStreamWaitEvent(0, g_evS, 0);
    {
        int total = M * (NOUT / 4);
        combine_kernel<<<(total + 255) / 256, 256>>>(hb, w_s, w_t, b_nd, out, M);
    }
}